// round 13
// baseline (speedup 1.0000x reference)
#include <cuda_runtime.h>
#include <cuda_fp16.h>
#include <math.h>
#include <stdint.h>

#define Bb   2
#define Tt   2048
#define Hh   16
#define Ss   64
#define EMBv 1024
#define NTOK (Bb*Tt)      // 4096 tokens
#define FF   (4*EMBv)     // 4096

// ---------------- scratch (static device globals) ---------------------------
__device__ __half g_xh [NTOK*EMBv];    // x in fp16
__device__ __half g_kqv[NTOK*Hh*3*Ss]; // [B,T,H,192] k|q*0.125*log2e|v (fp16)
__device__ __half g_res[NTOK*EMBv];    // attention output (fp16)
__device__ __half g_mha[NTOK*EMBv];    // proj output (fp16)
__device__ float  g_x1 [NTOK*EMBv];    // after first LN (fp32)
__device__ __half g_x1r[NTOK*EMBv];    // after first LN (fp16 copy)
__device__ __half g_h  [NTOK*FF];      // gelu(...) (fp16)
__device__ __half g_ff [NTOK*EMBv];    // h @ W2 + b (fp16)
__device__ __half g_wqt[192*Ss];       // Wkqv^T [192,64] fp16
__device__ __half g_wtp[EMBv*EMBv];    // Wproj^T [N,K] fp16
__device__ __half g_wt1[EMBv*FF];      // W1^T fp16
__device__ __half g_wt2[FF*EMBv];      // W2^T fp16

// ======================= helpers ===========================================
__device__ __forceinline__ uint32_t smem_u32(const void* p) {
    uint32_t a;
    asm("{ .reg .u64 t; cvta.to.shared.u64 t, %1; cvt.u32.u64 %0, t; }"
        : "=r"(a) : "l"(p));
    return a;
}
__device__ __forceinline__ void cpa16(uint32_t s, const void* g) {
    asm volatile("cp.async.cg.shared.global [%0], [%1], 16;\n" :: "r"(s), "l"(g));
}
__device__ __forceinline__ float ex2(float x) {
    float r;
    asm("ex2.approx.f32 %0, %1;" : "=f"(r) : "f"(x));
    return r;
}
__device__ __forceinline__ void mma_f16(float* c, const uint32_t* a, const uint32_t* b) {
    asm volatile(
        "mma.sync.aligned.m16n8k16.row.col.f32.f16.f16.f32 "
        "{%0,%1,%2,%3}, {%4,%5,%6,%7}, {%8,%9}, {%0,%1,%2,%3};"
        : "+f"(c[0]), "+f"(c[1]), "+f"(c[2]), "+f"(c[3])
        : "r"(a[0]), "r"(a[1]), "r"(a[2]), "r"(a[3]), "r"(b[0]), "r"(b[1]));
}
__device__ __forceinline__ void ldsm_x4(uint32_t& r0, uint32_t& r1,
                                        uint32_t& r2, uint32_t& r3, uint32_t a) {
    asm volatile("ldmatrix.sync.aligned.m8n8.x4.shared.b16 {%0,%1,%2,%3}, [%4];"
                 : "=r"(r0), "=r"(r1), "=r"(r2), "=r"(r3) : "r"(a));
}
__device__ __forceinline__ void ldsm_x4_trans(uint32_t& r0, uint32_t& r1,
                                              uint32_t& r2, uint32_t& r3, uint32_t a) {
    asm volatile("ldmatrix.sync.aligned.m8n8.x4.trans.shared.b16 {%0,%1,%2,%3}, [%4];"
                 : "=r"(r0), "=r"(r1), "=r"(r2), "=r"(r3) : "r"(a));
}
__device__ __forceinline__ void ldsm_x2_trans(uint32_t& r0, uint32_t& r1, uint32_t addr) {
    asm volatile("ldmatrix.sync.aligned.m8n8.x2.trans.shared.b16 {%0,%1}, [%2];"
                 : "=r"(r0), "=r"(r1) : "r"(addr));
}

// ======================= fp32 -> fp16 convert ==============================
__global__ __launch_bounds__(256)
void cvt_half_kernel(const float4* __restrict__ in, __half2* __restrict__ out, int n4)
{
    int i = blockIdx.x * 256 + threadIdx.x;
    if (i < n4) {
        float4 v = in[i];
        out[i*2+0] = __floats2half2_rn(v.x, v.y);
        out[i*2+1] = __floats2half2_rn(v.z, v.w);
    }
}

// ======================= weight transpose + fp16 ===========================
__global__ __launch_bounds__(256)
void transpose_kernel(const float* __restrict__ in, __half* __restrict__ out,
                      int R, int C)
{
    __shared__ float t[32][33];
    const int tx = threadIdx.x, ty = threadIdx.y;
    const int c = blockIdx.x * 32 + tx;
    const int r0 = blockIdx.y * 32;
    #pragma unroll
    for (int i = 0; i < 32; i += 8)
        t[ty + i][tx] = in[(size_t)(r0 + ty + i) * C + c];
    __syncthreads();
    const int oc = blockIdx.y * 32 + tx;
    const int or0 = blockIdx.x * 32;
    #pragma unroll
    for (int i = 0; i < 32; i += 8)
        out[(size_t)(or0 + ty + i) * R + oc] = __float2half_rn(t[tx][ty + i]);
}

// ======================= fp16 mma.sync GEMM ================================
// C[M,N] = epi(A[M,K] @ Bt[N,K]^T + bias). CTA 128x128, BK=64,
// 8 warps of 32x64, 3-stage cp.async, 2 CTAs/SM.
#define GLD     72
#define STAGEH  ((128+128)*GLD)
#define MMA_SMEM (3*STAGEH*(int)sizeof(__half))   // 110592 B

template<int EPI, typename OutT>
__global__ __launch_bounds__(256, 2)
void mma_gemm(const __half* __restrict__ A, const __half* __restrict__ Bt,
              const float* __restrict__ bias, OutT* __restrict__ C,
              int M, int N, int K)
{
    extern __shared__ __half smh[];
    const uint32_t smh_u = smem_u32(smh);
    const int tid  = threadIdx.x;
    const int lane = tid & 31;
    const int wid  = tid >> 5;
    const int m0 = (wid & 3) * 32;
    const int n0 = (wid >> 2) * 64;
    const int row0 = blockIdx.y * 128;
    const int col0 = blockIdx.x * 128;
    const int lq = lane >> 2;
    const int lr = lane & 3;
    const int rr = lane & 7, gg = lane >> 3;
    const int aRow = m0 + ((gg & 1) << 3) + rr;
    const int aCol = (gg & 2) << 2;
    const int bRow = n0 + ((gg >> 1) << 3) + rr;
    const int bCol = (gg & 1) << 3;

    float acc[2][8][4];
    #pragma unroll
    for (int i = 0; i < 2; i++)
        #pragma unroll
        for (int j = 0; j < 8; j++)
            #pragma unroll
            for (int k = 0; k < 4; k++) acc[i][j][k] = 0.f;

    auto issue = [&](int kt, int s) {
        const int k0 = kt * 64;
        __half* dstA = smh + s * STAGEH;
        __half* dstB = dstA + 128 * GLD;
        #pragma unroll
        for (int i = 0; i < 4; i++) {
            int e = tid + i * 256;
            int r = e >> 3, c8 = e & 7;
            cpa16(smem_u32(dstA + r * GLD + c8 * 8),
                  A + (size_t)(row0 + r) * K + k0 + c8 * 8);
            cpa16(smem_u32(dstB + r * GLD + c8 * 8),
                  Bt + (size_t)(col0 + r) * K + k0 + c8 * 8);
        }
        asm volatile("cp.async.commit_group;" ::: "memory");
    };

    const int NK = K / 64;
    issue(0, 0);
    issue(1, 1);

    for (int kt = 0; kt < NK; kt++) {
        const int s = kt % 3;
        if (kt == NK - 1) asm volatile("cp.async.wait_group 0;" ::: "memory");
        else              asm volatile("cp.async.wait_group 1;" ::: "memory");
        __syncthreads();
        if (kt + 2 < NK) issue(kt + 2, (kt + 2) % 3);

        const uint32_t sA_u = smh_u + (uint32_t)(s * STAGEH) * 2;
        const uint32_t sB_u = sA_u + (uint32_t)(128 * GLD) * 2;

        #pragma unroll
        for (int ks = 0; ks < 4; ks++) {
            uint32_t a[2][4], b[4][4];
            #pragma unroll
            for (int mi = 0; mi < 2; mi++)
                ldsm_x4(a[mi][0], a[mi][1], a[mi][2], a[mi][3],
                        sA_u + (uint32_t)((aRow + mi*16) * GLD + ks*16 + aCol) * 2);
            #pragma unroll
            for (int ng = 0; ng < 4; ng++)
                ldsm_x4(b[ng][0], b[ng][1], b[ng][2], b[ng][3],
                        sB_u + (uint32_t)((bRow + ng*16) * GLD + ks*16 + bCol) * 2);
            #pragma unroll
            for (int mi = 0; mi < 2; mi++)
                #pragma unroll
                for (int ni = 0; ni < 8; ni++)
                    mma_f16(acc[mi][ni], a[mi], &b[ni >> 1][(ni & 1) * 2]);
        }
    }

    #pragma unroll
    for (int mi = 0; mi < 2; mi++) {
        #pragma unroll
        for (int hh = 0; hh < 2; hh++) {
            const int r = row0 + m0 + mi * 16 + lq + hh * 8;
            #pragma unroll
            for (int ni = 0; ni < 8; ni++) {
                const int c = col0 + n0 + ni * 8 + 2 * lr;
                float vx = acc[mi][ni][hh * 2 + 0];
                float vy = acc[mi][ni][hh * 2 + 1];
                if (EPI >= 1) { vx += bias[c]; vy += bias[c + 1]; }
                if (EPI == 2) {
                    vx = 0.5f * vx * (1.f + erff(vx * 0.70710678118654752f));
                    vy = 0.5f * vy * (1.f + erff(vy * 0.70710678118654752f));
                }
                if (sizeof(OutT) == 2) {
                    *(__half2*)((__half*)C + (size_t)r * N + c) =
                        __floats2half2_rn(vx, vy);
                } else {
                    *(float2*)((float*)C + (size_t)r * N + c) = make_float2(vx, vy);
                }
            }
        }
    }
}

// ======================= kqv fp16 MMA (K=64, N=192) =========================
// q columns (64..127) pre-scaled by 0.125*log2(e) so attention can use ex2.
#define KQV_SMEM ((128+192)*GLD*(int)sizeof(__half))   // 46080 B

__global__ __launch_bounds__(192, 2)
void kqv_mma(const __half* __restrict__ xh, const __half* __restrict__ wqt,
             __half* __restrict__ kqv)
{
    extern __shared__ __half smh[];
    const uint32_t smh_u = smem_u32(smh);
    const int tid  = threadIdx.x;
    const int lane = tid & 31;
    const int wid  = tid >> 5;
    const int m0 = (wid & 1) * 64;
    const int n0 = (wid >> 1) * 64;     // 0,64,128
    const int row0 = blockIdx.x * 128;
    const int lq = lane >> 2, lr = lane & 3;
    const int rr = lane & 7, gg = lane >> 3;
    const int aRow = m0 + ((gg & 1) << 3) + rr;
    const int aCol = (gg & 2) << 2;
    const int bRow = n0 + ((gg >> 1) << 3) + rr;
    const int bCol = (gg & 1) << 3;
    // 0.125 * log2(e) for the q block (softmax done in exp2 domain)
    const float oscale = (n0 == 64) ? 0.18033688011112042f : 1.f;

    __half* sA = smh;
    __half* sB = smh + 128 * GLD;

    for (int e = tid; e < 1024; e += 192) {
        int r = e >> 3, c8 = e & 7;
        cpa16(smem_u32(sA + r * GLD + c8 * 8),
              xh + (size_t)(row0 + r) * 64 + c8 * 8);
    }
    #pragma unroll
    for (int i = 0; i < 8; i++) {
        int e = tid + i * 192;
        int r = e >> 3, c8 = e & 7;
        cpa16(smem_u32(sB + r * GLD + c8 * 8),
              wqt + (size_t)r * 64 + c8 * 8);
    }
    asm volatile("cp.async.commit_group;" ::: "memory");
    asm volatile("cp.async.wait_group 0;" ::: "memory");
    __syncthreads();

    float acc[4][8][4];
    #pragma unroll
    for (int i = 0; i < 4; i++)
        #pragma unroll
        for (int j = 0; j < 8; j++)
            #pragma unroll
            for (int k = 0; k < 4; k++) acc[i][j][k] = 0.f;

    const uint32_t sA_u = smh_u;
    const uint32_t sB_u = smh_u + (uint32_t)(128 * GLD) * 2;

    #pragma unroll
    for (int ks = 0; ks < 4; ks++) {
        uint32_t a[4][4], b[4][4];
        #pragma unroll
        for (int mi = 0; mi < 4; mi++)
            ldsm_x4(a[mi][0], a[mi][1], a[mi][2], a[mi][3],
                    sA_u + (uint32_t)((aRow + mi*16) * GLD + ks*16 + aCol) * 2);
        #pragma unroll
        for (int ng = 0; ng < 4; ng++)
            ldsm_x4(b[ng][0], b[ng][1], b[ng][2], b[ng][3],
                    sB_u + (uint32_t)((bRow + ng*16) * GLD + ks*16 + bCol) * 2);
        #pragma unroll
        for (int mi = 0; mi < 4; mi++)
            #pragma unroll
            for (int ni = 0; ni < 8; ni++)
                mma_f16(acc[mi][ni], a[mi], &b[ni >> 1][(ni & 1) * 2]);
    }

    #pragma unroll
    for (int mi = 0; mi < 4; mi++) {
        #pragma unroll
        for (int hh = 0; hh < 2; hh++) {
            const int r = row0 + m0 + mi * 16 + lq + hh * 8;
            #pragma unroll
            for (int ni = 0; ni < 8; ni++) {
                const int c = n0 + ni * 8 + 2 * lr;
                *(__half2*)(kqv + (size_t)r * 192 + c) =
                    __floats2half2_rn(acc[mi][ni][hh*2] * oscale,
                                      acc[mi][ni][hh*2+1] * oscale);
            }
        }
    }
}

// ---------------- fp16 flash attention (reg-P, MMA row-sums, ex2) -----------
#define ALD 72
#define ATTN_SMEM ((128*ALD + 2*64*ALD + 2*64*ALD)*(int)sizeof(__half))  // 55296

__global__ __launch_bounds__(256, 2)
void attn_mma(const __half* __restrict__ kqv, __half* __restrict__ res)
{
    extern __shared__ __half sma[];
    __half* Qs = sma;                     // 128 x ALD
    __half* Ks = Qs + 128*ALD;            // 2 x 64 x ALD
    __half* Vs = Ks + 2*64*ALD;           // 2 x 64 x ALD (cols 64..71: 1,0..0)

    const int bh = blockIdx.x;
    const int b  = bh >> 4;
    const int h  = bh & 15;
    const int q0 = blockIdx.y * 128;
    const int tid  = threadIdx.x;
    const int lane = tid & 31;
    const int wid  = tid >> 5;
    const int lq = lane >> 2, lr = lane & 3;
    const int m0 = wid * 16;
    const int rr = lane & 7, gg = lane >> 3;
    const int aRowL = ((gg & 1) << 3) + rr;
    const int aCol  = (gg & 2) << 2;
    const int bRowL = ((gg >> 1) << 3) + rr;
    const int bCol  = (gg & 1) << 3;
    const size_t rstr = (size_t)Hh * 3 * Ss;      // 3072 halves
    const __half* base = kqv + (size_t)(b * Tt) * rstr + h * 192;

    const uint32_t ks_u = smem_u32(Ks);
    const uint32_t vs_u = smem_u32(Vs);
    const uint32_t qs_u = smem_u32(Qs);

    // ones column for MMA row-sums: Vs[*][64]=1, [65..71]=0 (both stages).
    if (tid < 128) {
        __half* vr = Vs + (size_t)tid * ALD + 64;
        vr[0] = __float2half(1.f);
        #pragma unroll
        for (int i = 1; i < 8; i++) vr[i] = __float2half(0.f);
    }

    #pragma unroll
    for (int i = 0; i < 4; i++) {
        int e = tid + i * 256;
        int r = e >> 3, c8 = e & 7;
        cpa16(qs_u + (uint32_t)(r * ALD + c8 * 8) * 2,
              base + (size_t)(q0 + r) * rstr + 64 + c8 * 8);
    }
    asm volatile("cp.async.commit_group;" ::: "memory");

    auto issue_kv = [&](int kt, int s) {
        const __half* kb = base + (size_t)(kt * 64) * rstr;
        #pragma unroll
        for (int i = 0; i < 2; i++) {
            int e = tid + i * 256;
            int r = e >> 3, c8 = e & 7;
            cpa16(ks_u + (uint32_t)((s * 64 + r) * ALD + c8 * 8) * 2,
                  kb + (size_t)r * rstr + c8 * 8);
            cpa16(vs_u + (uint32_t)((s * 64 + r) * ALD + c8 * 8) * 2,
                  kb + (size_t)r * rstr + 128 + c8 * 8);
        }
        asm volatile("cp.async.commit_group;" ::: "memory");
    };

    issue_kv(0, 0);
    asm volatile("cp.async.wait_group 1;" ::: "memory");
    __syncthreads();

    uint32_t qf[4][4];
    #pragma unroll
    for (int ks = 0; ks < 4; ks++)
        ldsm_x4(qf[ks][0], qf[ks][1], qf[ks][2], qf[ks][3],
                qs_u + (uint32_t)((m0 + aRowL) * ALD + ks*16 + aCol) * 2);

    float mrow[2] = { -1e30f, -1e30f };
    float acc_o[8][4];
    float acc_l[4] = { 0.f, 0.f, 0.f, 0.f };      // row-sum accumulator
    #pragma unroll
    for (int nf = 0; nf < 8; nf++)
        #pragma unroll
        for (int c = 0; c < 4; c++) acc_o[nf][c] = 0.f;

    // PV fragment addressing: 16 k-rows from lane&15, upper half-warp +8 cols
    const uint32_t pvRow = (uint32_t)(lane & 15);
    const uint32_t pvColSh = (uint32_t)((lane >> 4) << 3);

    const int NT = Tt / 64;
    for (int kt = 0; kt < NT; kt++) {
        const int s = kt & 1;
        if (kt + 1 < NT) {
            issue_kv(kt + 1, s ^ 1);
            asm volatile("cp.async.wait_group 1;" ::: "memory");
        } else {
            asm volatile("cp.async.wait_group 0;" ::: "memory");
        }
        __syncthreads();

        const uint32_t k0_u = ks_u + (uint32_t)(s * 64 * ALD) * 2;

        // S (log2 domain; scale pre-folded into Q)
        float acc_s[8][4];
        #pragma unroll
        for (int nf = 0; nf < 8; nf++)
            #pragma unroll
            for (int c = 0; c < 4; c++) acc_s[nf][c] = 0.f;

        #pragma unroll
        for (int ks = 0; ks < 4; ks++) {
            uint32_t b[4][4];
            #pragma unroll
            for (int nf8 = 0; nf8 < 4; nf8++)
                ldsm_x4(b[nf8][0], b[nf8][1], b[nf8][2], b[nf8][3],
                        k0_u + (uint32_t)((bRowL + nf8*16) * ALD + ks*16 + bCol) * 2);
            #pragma unroll
            for (int nf = 0; nf < 8; nf++)
                mma_f16(acc_s[nf], qf[ks], &b[nf >> 1][(nf & 1) * 2]);
        }

        // online softmax (ex2); P in registers
        uint32_t ph[8][2];
        #pragma unroll
        for (int hh = 0; hh < 2; hh++) {
            float rmax = -1e30f;
            #pragma unroll
            for (int nf = 0; nf < 8; nf++)
                rmax = fmaxf(rmax, fmaxf(acc_s[nf][2*hh], acc_s[nf][2*hh+1]));
            rmax = fmaxf(rmax, __shfl_xor_sync(0xffffffffu, rmax, 1));
            rmax = fmaxf(rmax, __shfl_xor_sync(0xffffffffu, rmax, 2));
            float mn = fmaxf(mrow[hh], rmax);
            float scale = ex2(mrow[hh] - mn);
            #pragma unroll
            for (int nf = 0; nf < 8; nf++) {
                __half2 hp = __floats2half2_rn(ex2(acc_s[nf][2*hh]   - mn),
                                               ex2(acc_s[nf][2*hh+1] - mn));
                ph[nf][hh] = *(uint32_t*)&hp;
            }
            mrow[hh] = mn;
            #pragma unroll
            for (int nf = 0; nf < 8; nf++) {
                acc_o[nf][2*hh]   *= scale;
                acc_o[nf][2*hh+1] *= scale;
            }
            acc_l[2*hh]   *= scale;
            acc_l[2*hh+1] *= scale;
        }

        // O += P @ V ; l += P @ ones.  x4.trans: 4 mats per ldsm.
        const uint32_t v0_u = vs_u + (uint32_t)(s * 64 * ALD) * 2;
        #pragma unroll
        for (int ks = 0; ks < 4; ks++) {
            uint32_t a[4] = { ph[2*ks][0], ph[2*ks][1],
                              ph[2*ks+1][0], ph[2*ks+1][1] };
            const uint32_t rb4 = v0_u +
                (uint32_t)(((uint32_t)(ks * 16) + pvRow) * ALD + pvColSh) * 2;
            #pragma unroll
            for (int nf2 = 0; nf2 < 4; nf2++) {
                uint32_t b0, b1, b2, b3;
                ldsm_x4_trans(b0, b1, b2, b3, rb4 + (uint32_t)(nf2 * 16) * 2);
                uint32_t bfrA[2] = { b0, b1 };
                uint32_t bfrB[2] = { b2, b3 };
                mma_f16(acc_o[2*nf2],     a, bfrA);
                mma_f16(acc_o[2*nf2 + 1], a, bfrB);
            }
            // ones column (col 64)
            uint32_t c0, c1;
            ldsm_x2_trans(c0, c1, v0_u +
                (uint32_t)(((uint32_t)(ks * 16) + pvRow) * ALD + 64) * 2);
            uint32_t bfrL[2] = { c0, c1 };
            mma_f16(acc_l, a, bfrL);
        }
        __syncthreads();
    }

    // l lives in acc_l[0]/acc_l[2] of the lr==0 lane of each quad
    #pragma unroll
    for (int hh = 0; hh < 2; hh++) {
        float lsum = __shfl_sync(0xffffffffu, acc_l[2*hh], lane & 28);
        float inv = 1.f / lsum;
        int row = q0 + m0 + lq + 8 * hh;
        __half* orow = res + (size_t)(b * Tt + row) * EMBv + h * 64;
        #pragma unroll
        for (int nf = 0; nf < 8; nf++)
            *(__half2*)(orow + nf * 8 + 2 * lr) =
                __floats2half2_rn(acc_o[nf][2*hh] * inv, acc_o[nf][2*hh+1] * inv);
    }
}

// ---------------- fused residual add + LayerNorm (fp16 increment) ----------
__global__ __launch_bounds__(256)
void add_ln_kernel(const float* __restrict__ xa, const __half* __restrict__ xb,
                   const float* __restrict__ g, const float* __restrict__ bt,
                   float* __restrict__ out, __half* __restrict__ out_r)
{
    const int row = blockIdx.x;
    const int tid = threadIdx.x;
    const float* pa = xa + (size_t)row*EMBv;
    const __half* pb = xb + (size_t)row*EMBv;
    float v[4], s = 0.f, s2 = 0.f;
    #pragma unroll
    for (int i = 0; i < 4; i++) {
        int c = tid + i*256;
        v[i] = pa[c] + __half2float(pb[c]);
        s += v[i]; s2 += v[i]*v[i];
    }
    #pragma unroll
    for (int off = 16; off > 0; off >>= 1) {
        s  += __shfl_xor_sync(0xffffffffu, s,  off);
        s2 += __shfl_xor_sync(0xffffffffu, s2, off);
    }
    __shared__ float rs[8], rs2[8];
    int w = tid >> 5, lane = tid & 31;
    if (lane == 0) { rs[w] = s; rs2[w] = s2; }
    __syncthreads();
    if (w == 0) {
        float a  = (lane < 8) ? rs[lane]  : 0.f;
        float a2 = (lane < 8) ? rs2[lane] : 0.f;
        #pragma unroll
        for (int off = 4; off > 0; off >>= 1) {
            a  += __shfl_xor_sync(0xffffffffu, a,  off);
            a2 += __shfl_xor_sync(0xffffffffu, a2, off);
        }
        if (lane == 0) { rs[0] = a; rs2[0] = a2; }
    }
    __syncthreads();
    float mean = rs[0] * (1.f/EMBv);
    float var  = rs2[0] * (1.f/EMBv) - mean*mean;
    float inv  = rsqrtf(var + 1e-5f);
    #pragma unroll
    for (int i = 0; i < 4; i++) {
        int c = tid + i*256;
        float o = (v[i] - mean)*inv*g[c] + bt[c];
        out[(size_t)row*EMBv + c] = o;
        if (out_r) out_r[(size_t)row*EMBv + c] = __float2half_rn(o);
    }
}

// ---------------- launch ----------------------------------------------------
extern "C" void kernel_launch(void* const* d_in, const int* in_sizes, int n_in,
                              void* d_out, int out_size)
{
    const float* x     = (const float*)d_in[0];
    const float* Wkqv  = (const float*)d_in[1];
    const float* Wproj = (const float*)d_in[2];
    const float* g1    = (const float*)d_in[3];
    const float* b1    = (const float*)d_in[4];
    const float* W1    = (const float*)d_in[5];
    const float* bff1  = (const float*)d_in[6];
    const float* W2    = (const float*)d_in[7];
    const float* bff2  = (const float*)d_in[8];
    const float* g2    = (const float*)d_in[9];
    const float* b2    = (const float*)d_in[10];
    float* out = (float*)d_out;

    __half *xh, *kqv, *res, *mha, *x1r, *hbuf, *ff, *wqt, *wtp, *wt1, *wt2;
    float  *x1;
    cudaGetSymbolAddress((void**)&xh,   g_xh);
    cudaGetSymbolAddress((void**)&kqv,  g_kqv);
    cudaGetSymbolAddress((void**)&res,  g_res);
    cudaGetSymbolAddress((void**)&mha,  g_mha);
    cudaGetSymbolAddress((void**)&x1,   g_x1);
    cudaGetSymbolAddress((void**)&x1r,  g_x1r);
    cudaGetSymbolAddress((void**)&hbuf, g_h);
    cudaGetSymbolAddress((void**)&ff,   g_ff);
    cudaGetSymbolAddress((void**)&wqt,  g_wqt);
    cudaGetSymbolAddress((void**)&wtp,  g_wtp);
    cudaGetSymbolAddress((void**)&wt1,  g_wt1);
    cudaGetSymbolAddress((void**)&wt2,  g_wt2);

    cudaFuncSetAttribute((const void*)mma_gemm<0,__half>,
        cudaFuncAttributeMaxDynamicSharedMemorySize, MMA_SMEM);
    cudaFuncSetAttribute((const void*)mma_gemm<1,__half>,
        cudaFuncAttributeMaxDynamicSharedMemorySize, MMA_SMEM);
    cudaFuncSetAttribute((const void*)mma_gemm<2,__half>,
        cudaFuncAttributeMaxDynamicSharedMemorySize, MMA_SMEM);
    cudaFuncSetAttribute((const void*)attn_mma,
        cudaFuncAttributeMaxDynamicSharedMemorySize, ATTN_SMEM);
    cudaFuncSetAttribute((const void*)kqv_mma,
        cudaFuncAttributeMaxDynamicSharedMemorySize, KQV_SMEM);

    // order keeps attn_mma in the ncu profile slot (4th launch)
    cvt_half_kernel<<<(NTOK*EMBv/4 + 255)/256, 256>>>(
        (const float4*)x, (__half2*)xh, NTOK*EMBv/4);
    transpose_kernel<<<dim3(192/32, Ss/32), dim3(32,8)>>>(Wkqv, wqt, Ss, 192);
    kqv_mma<<<(NTOK*Hh)/128, 192, KQV_SMEM>>>(xh, wqt, kqv);
    attn_mma<<<dim3(Bb*Hh, Tt/128), 256, ATTN_SMEM>>>(kqv, res);
    transpose_kernel<<<dim3(EMBv/32, EMBv/32), dim3(32,8)>>>(Wproj, wtp, EMBv, EMBv);
    mma_gemm<0,__half><<<dim3(EMBv/128, NTOK/128), 256, MMA_SMEM>>>(
        res, wtp, nullptr, mha, NTOK, EMBv, EMBv);
    add_ln_kernel<<<NTOK, 256>>>(x, mha, g1, b1, x1, x1r);
    transpose_kernel<<<dim3(FF/32, EMBv/32), dim3(32,8)>>>(W1, wt1, EMBv, FF);
    mma_gemm<2,__half><<<dim3(FF/128, NTOK/128), 256, MMA_SMEM>>>(
        x1r, wt1, bff1, hbuf, NTOK, FF, EMBv);
    transpose_kernel<<<dim3(EMBv/32, FF/32), dim3(32,8)>>>(W2, wt2, FF, EMBv);
    mma_gemm<1,__half><<<dim3(EMBv/128, NTOK/128), 256, MMA_SMEM>>>(
        hbuf, wt2, bff2, ff, NTOK, EMBv, FF);
    add_ln_kernel<<<NTOK, 256>>>(x1, ff, g2, b2, out, nullptr);
}

// round 15
// speedup vs baseline: 1.5266x; 1.5266x over previous
#include <cuda_runtime.h>
#include <cuda_fp16.h>
#include <math.h>
#include <stdint.h>

#define Bb   2
#define Tt   2048
#define Hh   16
#define Ss   64
#define EMBv 1024
#define NTOK (Bb*Tt)      // 4096 tokens
#define FF   (4*EMBv)     // 4096

// ---------------- scratch (static device globals) ---------------------------
__device__ __half g_xh [NTOK*EMBv];    // x in fp16
__device__ __half g_kqv[NTOK*Hh*3*Ss]; // [B,T,H,192] k|q*0.125*log2e|v (fp16)
__device__ __half g_res[NTOK*EMBv];    // attention output (fp16)
__device__ __half g_mha[NTOK*EMBv];    // proj output (fp16)
__device__ float  g_x1 [NTOK*EMBv];    // after first LN (fp32)
__device__ __half g_x1r[NTOK*EMBv];    // after first LN (fp16 copy)
__device__ __half g_h  [NTOK*FF];      // gelu(...) (fp16)
__device__ __half g_ff [NTOK*EMBv];    // h @ W2 + b (fp16)
__device__ __half g_wqt[192*Ss];       // Wkqv^T [192,64] fp16
__device__ __half g_wtp[EMBv*EMBv];    // Wproj^T [N,K] fp16
__device__ __half g_wt1[EMBv*FF];      // W1^T fp16
__device__ __half g_wt2[FF*EMBv];      // W2^T fp16

// ======================= helpers ===========================================
__device__ __forceinline__ uint32_t smem_u32(const void* p) {
    uint32_t a;
    asm("{ .reg .u64 t; cvta.to.shared.u64 t, %1; cvt.u32.u64 %0, t; }"
        : "=r"(a) : "l"(p));
    return a;
}
__device__ __forceinline__ void cpa16(uint32_t s, const void* g) {
    asm volatile("cp.async.cg.shared.global [%0], [%1], 16;\n" :: "r"(s), "l"(g));
}
__device__ __forceinline__ float ex2(float x) {
    float r;
    asm("ex2.approx.f32 %0, %1;" : "=f"(r) : "f"(x));
    return r;
}
__device__ __forceinline__ void mma_f16(float* c, const uint32_t* a, const uint32_t* b) {
    asm volatile(
        "mma.sync.aligned.m16n8k16.row.col.f32.f16.f16.f32 "
        "{%0,%1,%2,%3}, {%4,%5,%6,%7}, {%8,%9}, {%0,%1,%2,%3};"
        : "+f"(c[0]), "+f"(c[1]), "+f"(c[2]), "+f"(c[3])
        : "r"(a[0]), "r"(a[1]), "r"(a[2]), "r"(a[3]), "r"(b[0]), "r"(b[1]));
}
__device__ __forceinline__ void ldsm_x4(uint32_t& r0, uint32_t& r1,
                                        uint32_t& r2, uint32_t& r3, uint32_t a) {
    asm volatile("ldmatrix.sync.aligned.m8n8.x4.shared.b16 {%0,%1,%2,%3}, [%4];"
                 : "=r"(r0), "=r"(r1), "=r"(r2), "=r"(r3) : "r"(a));
}
__device__ __forceinline__ void ldsm_x2_trans(uint32_t& r0, uint32_t& r1, uint32_t addr) {
    asm volatile("ldmatrix.sync.aligned.m8n8.x2.trans.shared.b16 {%0,%1}, [%2];"
                 : "=r"(r0), "=r"(r1) : "r"(addr));
}

// ======================= fp32 -> fp16 convert ==============================
__global__ __launch_bounds__(256)
void cvt_half_kernel(const float4* __restrict__ in, __half2* __restrict__ out, int n4)
{
    int i = blockIdx.x * 256 + threadIdx.x;
    if (i < n4) {
        float4 v = in[i];
        out[i*2+0] = __floats2half2_rn(v.x, v.y);
        out[i*2+1] = __floats2half2_rn(v.z, v.w);
    }
}

// ======================= weight transpose + fp16 ===========================
__global__ __launch_bounds__(256)
void transpose_kernel(const float* __restrict__ in, __half* __restrict__ out,
                      int R, int C)
{
    __shared__ float t[32][33];
    const int tx = threadIdx.x, ty = threadIdx.y;
    const int c = blockIdx.x * 32 + tx;
    const int r0 = blockIdx.y * 32;
    #pragma unroll
    for (int i = 0; i < 32; i += 8)
        t[ty + i][tx] = in[(size_t)(r0 + ty + i) * C + c];
    __syncthreads();
    const int oc = blockIdx.y * 32 + tx;
    const int or0 = blockIdx.x * 32;
    #pragma unroll
    for (int i = 0; i < 32; i += 8)
        out[(size_t)(or0 + ty + i) * R + oc] = __float2half_rn(t[tx][ty + i]);
}

// ======================= fp16 mma.sync GEMM ================================
// C[M,N] = epi(A[M,K] @ Bt[N,K]^T + bias). CTA 128x128, BK=64,
// 8 warps of 32x64, 3-stage cp.async, 2 CTAs/SM.
#define GLD     72
#define STAGEH  ((128+128)*GLD)
#define MMA_SMEM (3*STAGEH*(int)sizeof(__half))   // 110592 B

template<int EPI, typename OutT>
__global__ __launch_bounds__(256, 2)
void mma_gemm(const __half* __restrict__ A, const __half* __restrict__ Bt,
              const float* __restrict__ bias, OutT* __restrict__ C,
              int M, int N, int K)
{
    extern __shared__ __half smh[];
    const uint32_t smh_u = smem_u32(smh);
    const int tid  = threadIdx.x;
    const int lane = tid & 31;
    const int wid  = tid >> 5;
    const int m0 = (wid & 3) * 32;
    const int n0 = (wid >> 2) * 64;
    const int row0 = blockIdx.y * 128;
    const int col0 = blockIdx.x * 128;
    const int lq = lane >> 2;
    const int lr = lane & 3;
    const int rr = lane & 7, gg = lane >> 3;
    const int aRow = m0 + ((gg & 1) << 3) + rr;
    const int aCol = (gg & 2) << 2;
    const int bRow = n0 + ((gg >> 1) << 3) + rr;
    const int bCol = (gg & 1) << 3;

    float acc[2][8][4];
    #pragma unroll
    for (int i = 0; i < 2; i++)
        #pragma unroll
        for (int j = 0; j < 8; j++)
            #pragma unroll
            for (int k = 0; k < 4; k++) acc[i][j][k] = 0.f;

    auto issue = [&](int kt, int s) {
        const int k0 = kt * 64;
        __half* dstA = smh + s * STAGEH;
        __half* dstB = dstA + 128 * GLD;
        #pragma unroll
        for (int i = 0; i < 4; i++) {
            int e = tid + i * 256;
            int r = e >> 3, c8 = e & 7;
            cpa16(smem_u32(dstA + r * GLD + c8 * 8),
                  A + (size_t)(row0 + r) * K + k0 + c8 * 8);
            cpa16(smem_u32(dstB + r * GLD + c8 * 8),
                  Bt + (size_t)(col0 + r) * K + k0 + c8 * 8);
        }
        asm volatile("cp.async.commit_group;" ::: "memory");
    };

    const int NK = K / 64;
    issue(0, 0);
    issue(1, 1);

    for (int kt = 0; kt < NK; kt++) {
        const int s = kt % 3;
        if (kt == NK - 1) asm volatile("cp.async.wait_group 0;" ::: "memory");
        else              asm volatile("cp.async.wait_group 1;" ::: "memory");
        __syncthreads();
        if (kt + 2 < NK) issue(kt + 2, (kt + 2) % 3);

        const uint32_t sA_u = smh_u + (uint32_t)(s * STAGEH) * 2;
        const uint32_t sB_u = sA_u + (uint32_t)(128 * GLD) * 2;

        #pragma unroll
        for (int ks = 0; ks < 4; ks++) {
            uint32_t a[2][4], b[4][4];
            #pragma unroll
            for (int mi = 0; mi < 2; mi++)
                ldsm_x4(a[mi][0], a[mi][1], a[mi][2], a[mi][3],
                        sA_u + (uint32_t)((aRow + mi*16) * GLD + ks*16 + aCol) * 2);
            #pragma unroll
            for (int ng = 0; ng < 4; ng++)
                ldsm_x4(b[ng][0], b[ng][1], b[ng][2], b[ng][3],
                        sB_u + (uint32_t)((bRow + ng*16) * GLD + ks*16 + bCol) * 2);
            #pragma unroll
            for (int mi = 0; mi < 2; mi++)
                #pragma unroll
                for (int ni = 0; ni < 8; ni++)
                    mma_f16(acc[mi][ni], a[mi], &b[ni >> 1][(ni & 1) * 2]);
        }
    }

    #pragma unroll
    for (int mi = 0; mi < 2; mi++) {
        #pragma unroll
        for (int hh = 0; hh < 2; hh++) {
            const int r = row0 + m0 + mi * 16 + lq + hh * 8;
            #pragma unroll
            for (int ni = 0; ni < 8; ni++) {
                const int c = col0 + n0 + ni * 8 + 2 * lr;
                float vx = acc[mi][ni][hh * 2 + 0];
                float vy = acc[mi][ni][hh * 2 + 1];
                if (EPI >= 1) { vx += bias[c]; vy += bias[c + 1]; }
                if (EPI == 2) {
                    vx = 0.5f * vx * (1.f + erff(vx * 0.70710678118654752f));
                    vy = 0.5f * vy * (1.f + erff(vy * 0.70710678118654752f));
                }
                if (sizeof(OutT) == 2) {
                    *(__half2*)((__half*)C + (size_t)r * N + c) =
                        __floats2half2_rn(vx, vy);
                } else {
                    *(float2*)((float*)C + (size_t)r * N + c) = make_float2(vx, vy);
                }
            }
        }
    }
}

// ======================= kqv fp16 MMA (K=64, N=192) =========================
// q columns (64..127) pre-scaled by 0.125*log2(e) so attention can use ex2.
#define KQV_SMEM ((128+192)*GLD*(int)sizeof(__half))   // 46080 B

__global__ __launch_bounds__(192, 2)
void kqv_mma(const __half* __restrict__ xh, const __half* __restrict__ wqt,
             __half* __restrict__ kqv)
{
    extern __shared__ __half smh[];
    const uint32_t smh_u = smem_u32(smh);
    const int tid  = threadIdx.x;
    const int lane = tid & 31;
    const int wid  = tid >> 5;
    const int m0 = (wid & 1) * 64;
    const int n0 = (wid >> 1) * 64;     // 0,64,128
    const int row0 = blockIdx.x * 128;
    const int lq = lane >> 2, lr = lane & 3;
    const int rr = lane & 7, gg = lane >> 3;
    const int aRow = m0 + ((gg & 1) << 3) + rr;
    const int aCol = (gg & 2) << 2;
    const int bRow = n0 + ((gg >> 1) << 3) + rr;
    const int bCol = (gg & 1) << 3;
    // 0.125 * log2(e) for the q block (softmax done in exp2 domain)
    const float oscale = (n0 == 64) ? 0.18033688011112042f : 1.f;

    __half* sA = smh;
    __half* sB = smh + 128 * GLD;

    for (int e = tid; e < 1024; e += 192) {
        int r = e >> 3, c8 = e & 7;
        cpa16(smem_u32(sA + r * GLD + c8 * 8),
              xh + (size_t)(row0 + r) * 64 + c8 * 8);
    }
    #pragma unroll
    for (int i = 0; i < 8; i++) {
        int e = tid + i * 192;
        int r = e >> 3, c8 = e & 7;
        cpa16(smem_u32(sB + r * GLD + c8 * 8),
              wqt + (size_t)r * 64 + c8 * 8);
    }
    asm volatile("cp.async.commit_group;" ::: "memory");
    asm volatile("cp.async.wait_group 0;" ::: "memory");
    __syncthreads();

    float acc[4][8][4];
    #pragma unroll
    for (int i = 0; i < 4; i++)
        #pragma unroll
        for (int j = 0; j < 8; j++)
            #pragma unroll
            for (int k = 0; k < 4; k++) acc[i][j][k] = 0.f;

    const uint32_t sA_u = smh_u;
    const uint32_t sB_u = smh_u + (uint32_t)(128 * GLD) * 2;

    #pragma unroll
    for (int ks = 0; ks < 4; ks++) {
        uint32_t a[4][4], b[4][4];
        #pragma unroll
        for (int mi = 0; mi < 4; mi++)
            ldsm_x4(a[mi][0], a[mi][1], a[mi][2], a[mi][3],
                    sA_u + (uint32_t)((aRow + mi*16) * GLD + ks*16 + aCol) * 2);
        #pragma unroll
        for (int ng = 0; ng < 4; ng++)
            ldsm_x4(b[ng][0], b[ng][1], b[ng][2], b[ng][3],
                    sB_u + (uint32_t)((bRow + ng*16) * GLD + ks*16 + bCol) * 2);
        #pragma unroll
        for (int mi = 0; mi < 4; mi++)
            #pragma unroll
            for (int ni = 0; ni < 8; ni++)
                mma_f16(acc[mi][ni], a[mi], &b[ni >> 1][(ni & 1) * 2]);
    }

    #pragma unroll
    for (int mi = 0; mi < 4; mi++) {
        #pragma unroll
        for (int hh = 0; hh < 2; hh++) {
            const int r = row0 + m0 + mi * 16 + lq + hh * 8;
            #pragma unroll
            for (int ni = 0; ni < 8; ni++) {
                const int c = n0 + ni * 8 + 2 * lr;
                *(__half2*)(kqv + (size_t)r * 192 + c) =
                    __floats2half2_rn(acc[mi][ni][hh*2] * oscale,
                                      acc[mi][ni][hh*2+1] * oscale);
            }
        }
    }
}

// ---------------- fp16 flash attention (reg-P, MMA row-sums, ex2) -----------
#define ALD 72
#define ATTN_SMEM ((128*ALD + 2*64*ALD + 2*64*ALD)*(int)sizeof(__half))  // 55296

__global__ __launch_bounds__(256, 2)
void attn_mma(const __half* __restrict__ kqv, __half* __restrict__ res)
{
    extern __shared__ __half sma[];
    __half* Qs = sma;                     // 128 x ALD
    __half* Ks = Qs + 128*ALD;            // 2 x 64 x ALD
    __half* Vs = Ks + 2*64*ALD;           // 2 x 64 x ALD (cols 64..71: 1,0..0)

    const int bh = blockIdx.x;
    const int b  = bh >> 4;
    const int h  = bh & 15;
    const int q0 = blockIdx.y * 128;
    const int tid  = threadIdx.x;
    const int lane = tid & 31;
    const int wid  = tid >> 5;
    const int lq = lane >> 2, lr = lane & 3;
    const int m0 = wid * 16;
    const int rr = lane & 7, gg = lane >> 3;
    const int aRowL = ((gg & 1) << 3) + rr;
    const int aCol  = (gg & 2) << 2;
    const int bRowL = ((gg >> 1) << 3) + rr;
    const int bCol  = (gg & 1) << 3;
    const size_t rstr = (size_t)Hh * 3 * Ss;      // 3072 halves
    const __half* base = kqv + (size_t)(b * Tt) * rstr + h * 192;

    const uint32_t ks_u = smem_u32(Ks);
    const uint32_t vs_u = smem_u32(Vs);
    const uint32_t qs_u = smem_u32(Qs);

    // ones column for MMA row-sums: Vs[*][64]=1, [65..71]=0 (both stages).
    if (tid < 128) {
        __half* vr = Vs + (size_t)tid * ALD + 64;
        vr[0] = __float2half(1.f);
        #pragma unroll
        for (int i = 1; i < 8; i++) vr[i] = __float2half(0.f);
    }

    #pragma unroll
    for (int i = 0; i < 4; i++) {
        int e = tid + i * 256;
        int r = e >> 3, c8 = e & 7;
        cpa16(qs_u + (uint32_t)(r * ALD + c8 * 8) * 2,
              base + (size_t)(q0 + r) * rstr + 64 + c8 * 8);
    }
    asm volatile("cp.async.commit_group;" ::: "memory");

    auto issue_kv = [&](int kt, int s) {
        const __half* kb = base + (size_t)(kt * 64) * rstr;
        #pragma unroll
        for (int i = 0; i < 2; i++) {
            int e = tid + i * 256;
            int r = e >> 3, c8 = e & 7;
            cpa16(ks_u + (uint32_t)((s * 64 + r) * ALD + c8 * 8) * 2,
                  kb + (size_t)r * rstr + c8 * 8);
            cpa16(vs_u + (uint32_t)((s * 64 + r) * ALD + c8 * 8) * 2,
                  kb + (size_t)r * rstr + 128 + c8 * 8);
        }
        asm volatile("cp.async.commit_group;" ::: "memory");
    };

    issue_kv(0, 0);
    asm volatile("cp.async.wait_group 1;" ::: "memory");
    __syncthreads();

    uint32_t qf[4][4];
    #pragma unroll
    for (int ks = 0; ks < 4; ks++)
        ldsm_x4(qf[ks][0], qf[ks][1], qf[ks][2], qf[ks][3],
                qs_u + (uint32_t)((m0 + aRowL) * ALD + ks*16 + aCol) * 2);

    float mrow[2] = { -1e30f, -1e30f };
    float acc_o[8][4];
    float acc_l[4] = { 0.f, 0.f, 0.f, 0.f };      // row-sum accumulator
    #pragma unroll
    for (int nf = 0; nf < 8; nf++)
        #pragma unroll
        for (int c = 0; c < 4; c++) acc_o[nf][c] = 0.f;

    const int NT = Tt / 64;
    for (int kt = 0; kt < NT; kt++) {
        const int s = kt & 1;
        if (kt + 1 < NT) {
            issue_kv(kt + 1, s ^ 1);
            asm volatile("cp.async.wait_group 1;" ::: "memory");
        } else {
            asm volatile("cp.async.wait_group 0;" ::: "memory");
        }
        __syncthreads();

        const uint32_t k0_u = ks_u + (uint32_t)(s * 64 * ALD) * 2;

        // S (log2 domain; scale pre-folded into Q)
        float acc_s[8][4];
        #pragma unroll
        for (int nf = 0; nf < 8; nf++)
            #pragma unroll
            for (int c = 0; c < 4; c++) acc_s[nf][c] = 0.f;

        #pragma unroll
        for (int ks = 0; ks < 4; ks++) {
            uint32_t b[4][4];
            #pragma unroll
            for (int nf8 = 0; nf8 < 4; nf8++)
                ldsm_x4(b[nf8][0], b[nf8][1], b[nf8][2], b[nf8][3],
                        k0_u + (uint32_t)((bRowL + nf8*16) * ALD + ks*16 + bCol) * 2);
            #pragma unroll
            for (int nf = 0; nf < 8; nf++)
                mma_f16(acc_s[nf], qf[ks], &b[nf >> 1][(nf & 1) * 2]);
        }

        // online softmax (ex2); P in registers
        uint32_t ph[8][2];
        #pragma unroll
        for (int hh = 0; hh < 2; hh++) {
            float rmax = -1e30f;
            #pragma unroll
            for (int nf = 0; nf < 8; nf++)
                rmax = fmaxf(rmax, fmaxf(acc_s[nf][2*hh], acc_s[nf][2*hh+1]));
            rmax = fmaxf(rmax, __shfl_xor_sync(0xffffffffu, rmax, 1));
            rmax = fmaxf(rmax, __shfl_xor_sync(0xffffffffu, rmax, 2));
            float mn = fmaxf(mrow[hh], rmax);
            float scale = ex2(mrow[hh] - mn);
            #pragma unroll
            for (int nf = 0; nf < 8; nf++) {
                __half2 hp = __floats2half2_rn(ex2(acc_s[nf][2*hh]   - mn),
                                               ex2(acc_s[nf][2*hh+1] - mn));
                ph[nf][hh] = *(uint32_t*)&hp;
            }
            mrow[hh] = mn;
            #pragma unroll
            for (int nf = 0; nf < 8; nf++) {
                acc_o[nf][2*hh]   *= scale;
                acc_o[nf][2*hh+1] *= scale;
            }
            acc_l[2*hh]   *= scale;
            acc_l[2*hh+1] *= scale;
        }

        // O += P @ V ; l += P @ ones (9th n-fragment)
        const uint32_t v0_u = vs_u + (uint32_t)(s * 64 * ALD) * 2;
        #pragma unroll
        for (int ks = 0; ks < 4; ks++) {
            uint32_t a[4] = { ph[2*ks][0], ph[2*ks][1],
                              ph[2*ks+1][0], ph[2*ks+1][1] };
            const uint32_t rowaddr = v0_u +
                (uint32_t)((ks * 16 + (lane & 15)) * ALD) * 2;
            #pragma unroll
            for (int nf = 0; nf < 9; nf++) {
                uint32_t b0, b1;
                ldsm_x2_trans(b0, b1, rowaddr + (uint32_t)(nf * 8) * 2);
                uint32_t bfr[2] = { b0, b1 };
                mma_f16(nf < 8 ? acc_o[nf] : acc_l, a, bfr);
            }
        }
        __syncthreads();
    }

    // l lives in acc_l[0]/acc_l[2] of the lr==0 lane of each quad
    #pragma unroll
    for (int hh = 0; hh < 2; hh++) {
        float lsum = __shfl_sync(0xffffffffu, acc_l[2*hh], lane & 28);
        float inv = 1.f / lsum;
        int row = q0 + m0 + lq + 8 * hh;
        __half* orow = res + (size_t)(b * Tt + row) * EMBv + h * 64;
        #pragma unroll
        for (int nf = 0; nf < 8; nf++)
            *(__half2*)(orow + nf * 8 + 2 * lr) =
                __floats2half2_rn(acc_o[nf][2*hh] * inv, acc_o[nf][2*hh+1] * inv);
    }
}

// ---------------- fused residual add + LayerNorm (fp16 increment) ----------
__global__ __launch_bounds__(256)
void add_ln_kernel(const float* __restrict__ xa, const __half* __restrict__ xb,
                   const float* __restrict__ g, const float* __restrict__ bt,
                   float* __restrict__ out, __half* __restrict__ out_r)
{
    const int row = blockIdx.x;
    const int tid = threadIdx.x;
    const float* pa = xa + (size_t)row*EMBv;
    const __half* pb = xb + (size_t)row*EMBv;
    float v[4], s = 0.f, s2 = 0.f;
    #pragma unroll
    for (int i = 0; i < 4; i++) {
        int c = tid + i*256;
        v[i] = pa[c] + __half2float(pb[c]);
        s += v[i]; s2 += v[i]*v[i];
    }
    #pragma unroll
    for (int off = 16; off > 0; off >>= 1) {
        s  += __shfl_xor_sync(0xffffffffu, s,  off);
        s2 += __shfl_xor_sync(0xffffffffu, s2, off);
    }
    __shared__ float rs[8], rs2[8];
    int w = tid >> 5, lane = tid & 31;
    if (lane == 0) { rs[w] = s; rs2[w] = s2; }
    __syncthreads();
    if (w == 0) {
        float a  = (lane < 8) ? rs[lane]  : 0.f;
        float a2 = (lane < 8) ? rs2[lane] : 0.f;
        #pragma unroll
        for (int off = 4; off > 0; off >>= 1) {
            a  += __shfl_xor_sync(0xffffffffu, a,  off);
            a2 += __shfl_xor_sync(0xffffffffu, a2, off);
        }
        if (lane == 0) { rs[0] = a; rs2[0] = a2; }
    }
    __syncthreads();
    float mean = rs[0] * (1.f/EMBv);
    float var  = rs2[0] * (1.f/EMBv) - mean*mean;
    float inv  = rsqrtf(var + 1e-5f);
    #pragma unroll
    for (int i = 0; i < 4; i++) {
        int c = tid + i*256;
        float o = (v[i] - mean)*inv*g[c] + bt[c];
        out[(size_t)row*EMBv + c] = o;
        if (out_r) out_r[(size_t)row*EMBv + c] = __float2half_rn(o);
    }
}

// ---------------- launch ----------------------------------------------------
extern "C" void kernel_launch(void* const* d_in, const int* in_sizes, int n_in,
                              void* d_out, int out_size)
{
    const float* x     = (const float*)d_in[0];
    const float* Wkqv  = (const float*)d_in[1];
    const float* Wproj = (const float*)d_in[2];
    const float* g1    = (const float*)d_in[3];
    const float* b1    = (const float*)d_in[4];
    const float* W1    = (const float*)d_in[5];
    const float* bff1  = (const float*)d_in[6];
    const float* W2    = (const float*)d_in[7];
    const float* bff2  = (const float*)d_in[8];
    const float* g2    = (const float*)d_in[9];
    const float* b2    = (const float*)d_in[10];
    float* out = (float*)d_out;

    __half *xh, *kqv, *res, *mha, *x1r, *hbuf, *ff, *wqt, *wtp, *wt1, *wt2;
    float  *x1;
    cudaGetSymbolAddress((void**)&xh,   g_xh);
    cudaGetSymbolAddress((void**)&kqv,  g_kqv);
    cudaGetSymbolAddress((void**)&res,  g_res);
    cudaGetSymbolAddress((void**)&mha,  g_mha);
    cudaGetSymbolAddress((void**)&x1,   g_x1);
    cudaGetSymbolAddress((void**)&x1r,  g_x1r);
    cudaGetSymbolAddress((void**)&hbuf, g_h);
    cudaGetSymbolAddress((void**)&ff,   g_ff);
    cudaGetSymbolAddress((void**)&wqt,  g_wqt);
    cudaGetSymbolAddress((void**)&wtp,  g_wtp);
    cudaGetSymbolAddress((void**)&wt1,  g_wt1);
    cudaGetSymbolAddress((void**)&wt2,  g_wt2);

    cudaFuncSetAttribute((const void*)mma_gemm<0,__half>,
        cudaFuncAttributeMaxDynamicSharedMemorySize, MMA_SMEM);
    cudaFuncSetAttribute((const void*)mma_gemm<1,__half>,
        cudaFuncAttributeMaxDynamicSharedMemorySize, MMA_SMEM);
    cudaFuncSetAttribute((const void*)mma_gemm<2,__half>,
        cudaFuncAttributeMaxDynamicSharedMemorySize, MMA_SMEM);
    cudaFuncSetAttribute((const void*)attn_mma,
        cudaFuncAttributeMaxDynamicSharedMemorySize, ATTN_SMEM);
    cudaFuncSetAttribute((const void*)kqv_mma,
        cudaFuncAttributeMaxDynamicSharedMemorySize, KQV_SMEM);

    // order keeps attn_mma in the ncu profile slot (4th launch)
    cvt_half_kernel<<<(NTOK*EMBv/4 + 255)/256, 256>>>(
        (const float4*)x, (__half2*)xh, NTOK*EMBv/4);
    transpose_kernel<<<dim3(192/32, Ss/32), dim3(32,8)>>>(Wkqv, wqt, Ss, 192);
    kqv_mma<<<(NTOK*Hh)/128, 192, KQV_SMEM>>>(xh, wqt, kqv);
    attn_mma<<<dim3(Bb*Hh, Tt/128), 256, ATTN_SMEM>>>(kqv, res);
    transpose_kernel<<<dim3(EMBv/32, EMBv/32), dim3(32,8)>>>(Wproj, wtp, EMBv, EMBv);
    mma_gemm<0,__half><<<dim3(EMBv/128, NTOK/128), 256, MMA_SMEM>>>(
        res, wtp, nullptr, mha, NTOK, EMBv, EMBv);
    add_ln_kernel<<<NTOK, 256>>>(x, mha, g1, b1, x1, x1r);
    transpose_kernel<<<dim3(FF/32, EMBv/32), dim3(32,8)>>>(W1, wt1, EMBv, FF);
    mma_gemm<2,__half><<<dim3(FF/128, NTOK/128), 256, MMA_SMEM>>>(
        x1r, wt1, bff1, hbuf, NTOK, FF, EMBv);
    transpose_kernel<<<dim3(EMBv/32, FF/32), dim3(32,8)>>>(W2, wt2, FF, EMBv);
    mma_gemm<1,__half><<<dim3(EMBv/128, NTOK/128), 256, MMA_SMEM>>>(
        hbuf, wt2, bff2, ff, NTOK, EMBv, FF);
    add_ln_kernel<<<NTOK, 256>>>(x1, ff, g2, b2, out, nullptr);
}

// round 16
// speedup vs baseline: 1.5455x; 1.0124x over previous
#include <cuda_runtime.h>
#include <cuda_fp16.h>
#include <math.h>
#include <stdint.h>

#define Bb   2
#define Tt   2048
#define Hh   16
#define Ss   64
#define EMBv 1024
#define NTOK (Bb*Tt)      // 4096 tokens
#define FF   (4*EMBv)     // 4096

// ---------------- scratch (static device globals) ---------------------------
__device__ __half g_xh [NTOK*EMBv];    // x in fp16
__device__ __half g_kqv[NTOK*Hh*3*Ss]; // [B,T,H,192] k|q*0.125*log2e|v (fp16)
__device__ __half g_res[NTOK*EMBv];    // attention output (fp16)
__device__ __half g_mha[NTOK*EMBv];    // proj output (fp16)
__device__ float  g_x1 [NTOK*EMBv];    // after first LN (fp32)
__device__ __half g_x1r[NTOK*EMBv];    // after first LN (fp16 copy)
__device__ __half g_h  [NTOK*FF];      // gelu(...) (fp16)
__device__ __half g_ff [NTOK*EMBv];    // h @ W2 + b (fp16)
__device__ __half g_wqt[192*Ss];       // Wkqv^T [192,64] fp16
__device__ __half g_wtp[EMBv*EMBv];    // Wproj^T [N,K] fp16
__device__ __half g_wt1[EMBv*FF];      // W1^T fp16
__device__ __half g_wt2[FF*EMBv];      // W2^T fp16

// ======================= helpers ===========================================
__device__ __forceinline__ uint32_t smem_u32(const void* p) {
    uint32_t a;
    asm("{ .reg .u64 t; cvta.to.shared.u64 t, %1; cvt.u32.u64 %0, t; }"
        : "=r"(a) : "l"(p));
    return a;
}
__device__ __forceinline__ void cpa16(uint32_t s, const void* g) {
    asm volatile("cp.async.cg.shared.global [%0], [%1], 16;\n" :: "r"(s), "l"(g));
}
__device__ __forceinline__ float ex2(float x) {
    float r;
    asm("ex2.approx.f32 %0, %1;" : "=f"(r) : "f"(x));
    return r;
}
__device__ __forceinline__ void mma_f16(float* c, const uint32_t* a, const uint32_t* b) {
    asm volatile(
        "mma.sync.aligned.m16n8k16.row.col.f32.f16.f16.f32 "
        "{%0,%1,%2,%3}, {%4,%5,%6,%7}, {%8,%9}, {%0,%1,%2,%3};"
        : "+f"(c[0]), "+f"(c[1]), "+f"(c[2]), "+f"(c[3])
        : "r"(a[0]), "r"(a[1]), "r"(a[2]), "r"(a[3]), "r"(b[0]), "r"(b[1]));
}
__device__ __forceinline__ void ldsm_x4(uint32_t& r0, uint32_t& r1,
                                        uint32_t& r2, uint32_t& r3, uint32_t a) {
    asm volatile("ldmatrix.sync.aligned.m8n8.x4.shared.b16 {%0,%1,%2,%3}, [%4];"
                 : "=r"(r0), "=r"(r1), "=r"(r2), "=r"(r3) : "r"(a));
}
__device__ __forceinline__ void ldsm_x2_trans(uint32_t& r0, uint32_t& r1, uint32_t addr) {
    asm volatile("ldmatrix.sync.aligned.m8n8.x2.trans.shared.b16 {%0,%1}, [%2];"
                 : "=r"(r0), "=r"(r1) : "r"(addr));
}

// ======================= fp32 -> fp16 convert ==============================
__global__ __launch_bounds__(256)
void cvt_half_kernel(const float4* __restrict__ in, __half2* __restrict__ out, int n4)
{
    int i = blockIdx.x * 256 + threadIdx.x;
    if (i < n4) {
        float4 v = in[i];
        out[i*2+0] = __floats2half2_rn(v.x, v.y);
        out[i*2+1] = __floats2half2_rn(v.z, v.w);
    }
}

// ======================= weight transpose + fp16 ===========================
__global__ __launch_bounds__(256)
void transpose_kernel(const float* __restrict__ in, __half* __restrict__ out,
                      int R, int C)
{
    __shared__ float t[32][33];
    const int tx = threadIdx.x, ty = threadIdx.y;
    const int c = blockIdx.x * 32 + tx;
    const int r0 = blockIdx.y * 32;
    #pragma unroll
    for (int i = 0; i < 32; i += 8)
        t[ty + i][tx] = in[(size_t)(r0 + ty + i) * C + c];
    __syncthreads();
    const int oc = blockIdx.y * 32 + tx;
    const int or0 = blockIdx.x * 32;
    #pragma unroll
    for (int i = 0; i < 32; i += 8)
        out[(size_t)(or0 + ty + i) * R + oc] = __float2half_rn(t[tx][ty + i]);
}

// ======================= fp16 mma.sync GEMM ================================
// C[M,N] = epi(A[M,K] @ Bt[N,K]^T + bias). CTA 128x128, BK=64,
// 8 warps of 32x64, 3-stage cp.async, 2 CTAs/SM.
#define GLD     72
#define STAGEH  ((128+128)*GLD)
#define MMA_SMEM (3*STAGEH*(int)sizeof(__half))   // 110592 B

template<int EPI, typename OutT>
__global__ __launch_bounds__(256, 2)
void mma_gemm(const __half* __restrict__ A, const __half* __restrict__ Bt,
              const float* __restrict__ bias, OutT* __restrict__ C,
              int M, int N, int K)
{
    extern __shared__ __half smh[];
    const uint32_t smh_u = smem_u32(smh);
    const int tid  = threadIdx.x;
    const int lane = tid & 31;
    const int wid  = tid >> 5;
    const int m0 = (wid & 3) * 32;
    const int n0 = (wid >> 2) * 64;
    const int row0 = blockIdx.y * 128;
    const int col0 = blockIdx.x * 128;
    const int lq = lane >> 2;
    const int lr = lane & 3;
    const int rr = lane & 7, gg = lane >> 3;
    const int aRow = m0 + ((gg & 1) << 3) + rr;
    const int aCol = (gg & 2) << 2;
    const int bRow = n0 + ((gg >> 1) << 3) + rr;
    const int bCol = (gg & 1) << 3;

    float acc[2][8][4];
    #pragma unroll
    for (int i = 0; i < 2; i++)
        #pragma unroll
        for (int j = 0; j < 8; j++)
            #pragma unroll
            for (int k = 0; k < 4; k++) acc[i][j][k] = 0.f;

    auto issue = [&](int kt, int s) {
        const int k0 = kt * 64;
        __half* dstA = smh + s * STAGEH;
        __half* dstB = dstA + 128 * GLD;
        #pragma unroll
        for (int i = 0; i < 4; i++) {
            int e = tid + i * 256;
            int r = e >> 3, c8 = e & 7;
            cpa16(smem_u32(dstA + r * GLD + c8 * 8),
                  A + (size_t)(row0 + r) * K + k0 + c8 * 8);
            cpa16(smem_u32(dstB + r * GLD + c8 * 8),
                  Bt + (size_t)(col0 + r) * K + k0 + c8 * 8);
        }
        asm volatile("cp.async.commit_group;" ::: "memory");
    };

    const int NK = K / 64;
    issue(0, 0);
    issue(1, 1);

    for (int kt = 0; kt < NK; kt++) {
        const int s = kt % 3;
        if (kt == NK - 1) asm volatile("cp.async.wait_group 0;" ::: "memory");
        else              asm volatile("cp.async.wait_group 1;" ::: "memory");
        __syncthreads();
        if (kt + 2 < NK) issue(kt + 2, (kt + 2) % 3);

        const uint32_t sA_u = smh_u + (uint32_t)(s * STAGEH) * 2;
        const uint32_t sB_u = sA_u + (uint32_t)(128 * GLD) * 2;

        #pragma unroll
        for (int ks = 0; ks < 4; ks++) {
            uint32_t a[2][4], b[4][4];
            #pragma unroll
            for (int mi = 0; mi < 2; mi++)
                ldsm_x4(a[mi][0], a[mi][1], a[mi][2], a[mi][3],
                        sA_u + (uint32_t)((aRow + mi*16) * GLD + ks*16 + aCol) * 2);
            #pragma unroll
            for (int ng = 0; ng < 4; ng++)
                ldsm_x4(b[ng][0], b[ng][1], b[ng][2], b[ng][3],
                        sB_u + (uint32_t)((bRow + ng*16) * GLD + ks*16 + bCol) * 2);
            #pragma unroll
            for (int mi = 0; mi < 2; mi++)
                #pragma unroll
                for (int ni = 0; ni < 8; ni++)
                    mma_f16(acc[mi][ni], a[mi], &b[ni >> 1][(ni & 1) * 2]);
        }
    }

    #pragma unroll
    for (int mi = 0; mi < 2; mi++) {
        #pragma unroll
        for (int hh = 0; hh < 2; hh++) {
            const int r = row0 + m0 + mi * 16 + lq + hh * 8;
            #pragma unroll
            for (int ni = 0; ni < 8; ni++) {
                const int c = col0 + n0 + ni * 8 + 2 * lr;
                float vx = acc[mi][ni][hh * 2 + 0];
                float vy = acc[mi][ni][hh * 2 + 1];
                if (EPI >= 1) { vx += bias[c]; vy += bias[c + 1]; }
                if (EPI == 2) {
                    vx = 0.5f * vx * (1.f + erff(vx * 0.70710678118654752f));
                    vy = 0.5f * vy * (1.f + erff(vy * 0.70710678118654752f));
                }
                if (sizeof(OutT) == 2) {
                    *(__half2*)((__half*)C + (size_t)r * N + c) =
                        __floats2half2_rn(vx, vy);
                } else {
                    *(float2*)((float*)C + (size_t)r * N + c) = make_float2(vx, vy);
                }
            }
        }
    }
}

// ======================= kqv fp16 MMA (K=64, N=192) =========================
// q columns (64..127) pre-scaled by 0.125*log2(e) so attention can use ex2.
#define KQV_SMEM ((128+192)*GLD*(int)sizeof(__half))   // 46080 B

__global__ __launch_bounds__(192, 2)
void kqv_mma(const __half* __restrict__ xh, const __half* __restrict__ wqt,
             __half* __restrict__ kqv)
{
    extern __shared__ __half smh[];
    const uint32_t smh_u = smem_u32(smh);
    const int tid  = threadIdx.x;
    const int lane = tid & 31;
    const int wid  = tid >> 5;
    const int m0 = (wid & 1) * 64;
    const int n0 = (wid >> 1) * 64;     // 0,64,128
    const int row0 = blockIdx.x * 128;
    const int lq = lane >> 2, lr = lane & 3;
    const int rr = lane & 7, gg = lane >> 3;
    const int aRow = m0 + ((gg & 1) << 3) + rr;
    const int aCol = (gg & 2) << 2;
    const int bRow = n0 + ((gg >> 1) << 3) + rr;
    const int bCol = (gg & 1) << 3;
    // 0.125 * log2(e) for the q block (softmax done in exp2 domain)
    const float oscale = (n0 == 64) ? 0.18033688011112042f : 1.f;

    __half* sA = smh;
    __half* sB = smh + 128 * GLD;

    for (int e = tid; e < 1024; e += 192) {
        int r = e >> 3, c8 = e & 7;
        cpa16(smem_u32(sA + r * GLD + c8 * 8),
              xh + (size_t)(row0 + r) * 64 + c8 * 8);
    }
    #pragma unroll
    for (int i = 0; i < 8; i++) {
        int e = tid + i * 192;
        int r = e >> 3, c8 = e & 7;
        cpa16(smem_u32(sB + r * GLD + c8 * 8),
              wqt + (size_t)r * 64 + c8 * 8);
    }
    asm volatile("cp.async.commit_group;" ::: "memory");
    asm volatile("cp.async.wait_group 0;" ::: "memory");
    __syncthreads();

    float acc[4][8][4];
    #pragma unroll
    for (int i = 0; i < 4; i++)
        #pragma unroll
        for (int j = 0; j < 8; j++)
            #pragma unroll
            for (int k = 0; k < 4; k++) acc[i][j][k] = 0.f;

    const uint32_t sA_u = smh_u;
    const uint32_t sB_u = smh_u + (uint32_t)(128 * GLD) * 2;

    #pragma unroll
    for (int ks = 0; ks < 4; ks++) {
        uint32_t a[4][4], b[4][4];
        #pragma unroll
        for (int mi = 0; mi < 4; mi++)
            ldsm_x4(a[mi][0], a[mi][1], a[mi][2], a[mi][3],
                    sA_u + (uint32_t)((aRow + mi*16) * GLD + ks*16 + aCol) * 2);
        #pragma unroll
        for (int ng = 0; ng < 4; ng++)
            ldsm_x4(b[ng][0], b[ng][1], b[ng][2], b[ng][3],
                    sB_u + (uint32_t)((bRow + ng*16) * GLD + ks*16 + bCol) * 2);
        #pragma unroll
        for (int mi = 0; mi < 4; mi++)
            #pragma unroll
            for (int ni = 0; ni < 8; ni++)
                mma_f16(acc[mi][ni], a[mi], &b[ni >> 1][(ni & 1) * 2]);
    }

    #pragma unroll
    for (int mi = 0; mi < 4; mi++) {
        #pragma unroll
        for (int hh = 0; hh < 2; hh++) {
            const int r = row0 + m0 + mi * 16 + lq + hh * 8;
            #pragma unroll
            for (int ni = 0; ni < 8; ni++) {
                const int c = n0 + ni * 8 + 2 * lr;
                *(__half2*)(kqv + (size_t)r * 192 + c) =
                    __floats2half2_rn(acc[mi][ni][hh*2] * oscale,
                                      acc[mi][ni][hh*2+1] * oscale);
            }
        }
    }
}

// ---------------- fp16 flash attention (reg-P, MMA row-sums, ex2) -----------
#define ALD 72
#define ATTN_SMEM ((128*ALD + 2*64*ALD + 2*64*ALD)*(int)sizeof(__half))  // 55296

__global__ __launch_bounds__(256, 2)
void attn_mma(const __half* __restrict__ kqv, __half* __restrict__ res)
{
    extern __shared__ __half sma[];
    __half* Qs = sma;                     // 128 x ALD
    __half* Ks = Qs + 128*ALD;            // 2 x 64 x ALD
    __half* Vs = Ks + 2*64*ALD;           // 2 x 64 x ALD (cols 64..71: 1,0..0)

    const int bh = blockIdx.x;
    const int b  = bh >> 4;
    const int h  = bh & 15;
    const int q0 = blockIdx.y * 128;
    const int tid  = threadIdx.x;
    const int lane = tid & 31;
    const int wid  = tid >> 5;
    const int lq = lane >> 2, lr = lane & 3;
    const int m0 = wid * 16;
    const int rr = lane & 7, gg = lane >> 3;
    const int aRowL = ((gg & 1) << 3) + rr;
    const int aCol  = (gg & 2) << 2;
    const int bRowL = ((gg >> 1) << 3) + rr;
    const int bCol  = (gg & 1) << 3;
    const size_t rstr = (size_t)Hh * 3 * Ss;      // 3072 halves
    const __half* base = kqv + (size_t)(b * Tt) * rstr + h * 192;

    const uint32_t ks_u = smem_u32(Ks);
    const uint32_t vs_u = smem_u32(Vs);
    const uint32_t qs_u = smem_u32(Qs);

    // ones column for MMA row-sums: Vs[*][64]=1, [65..71]=0 (both stages).
    if (tid < 128) {
        __half* vr = Vs + (size_t)tid * ALD + 64;
        vr[0] = __float2half(1.f);
        #pragma unroll
        for (int i = 1; i < 8; i++) vr[i] = __float2half(0.f);
    }

    #pragma unroll
    for (int i = 0; i < 4; i++) {
        int e = tid + i * 256;
        int r = e >> 3, c8 = e & 7;
        cpa16(qs_u + (uint32_t)(r * ALD + c8 * 8) * 2,
              base + (size_t)(q0 + r) * rstr + 64 + c8 * 8);
    }
    asm volatile("cp.async.commit_group;" ::: "memory");

    auto issue_kv = [&](int kt, int s) {
        const __half* kb = base + (size_t)(kt * 64) * rstr;
        #pragma unroll
        for (int i = 0; i < 2; i++) {
            int e = tid + i * 256;
            int r = e >> 3, c8 = e & 7;
            cpa16(ks_u + (uint32_t)((s * 64 + r) * ALD + c8 * 8) * 2,
                  kb + (size_t)r * rstr + c8 * 8);
            cpa16(vs_u + (uint32_t)((s * 64 + r) * ALD + c8 * 8) * 2,
                  kb + (size_t)r * rstr + 128 + c8 * 8);
        }
        asm volatile("cp.async.commit_group;" ::: "memory");
    };

    issue_kv(0, 0);
    asm volatile("cp.async.wait_group 1;" ::: "memory");
    __syncthreads();

    uint32_t qf[4][4];
    #pragma unroll
    for (int ks = 0; ks < 4; ks++)
        ldsm_x4(qf[ks][0], qf[ks][1], qf[ks][2], qf[ks][3],
                qs_u + (uint32_t)((m0 + aRowL) * ALD + ks*16 + aCol) * 2);

    float mrow[2] = { -1e30f, -1e30f };
    float acc_o[8][4];
    float acc_l[4] = { 0.f, 0.f, 0.f, 0.f };      // row-sum accumulator
    #pragma unroll
    for (int nf = 0; nf < 8; nf++)
        #pragma unroll
        for (int c = 0; c < 4; c++) acc_o[nf][c] = 0.f;

    const int NT = Tt / 64;
    for (int kt = 0; kt < NT; kt++) {
        const int s = kt & 1;
        if (kt + 1 < NT) {
            issue_kv(kt + 1, s ^ 1);
            asm volatile("cp.async.wait_group 1;" ::: "memory");
        } else {
            asm volatile("cp.async.wait_group 0;" ::: "memory");
        }
        __syncthreads();

        const uint32_t k0_u = ks_u + (uint32_t)(s * 64 * ALD) * 2;

        // S (log2 domain; scale pre-folded into Q)
        float acc_s[8][4];
        #pragma unroll
        for (int nf = 0; nf < 8; nf++)
            #pragma unroll
            for (int c = 0; c < 4; c++) acc_s[nf][c] = 0.f;

        #pragma unroll
        for (int ks = 0; ks < 4; ks++) {
            uint32_t b[4][4];
            #pragma unroll
            for (int nf8 = 0; nf8 < 4; nf8++)
                ldsm_x4(b[nf8][0], b[nf8][1], b[nf8][2], b[nf8][3],
                        k0_u + (uint32_t)((bRowL + nf8*16) * ALD + ks*16 + bCol) * 2);
            #pragma unroll
            for (int nf = 0; nf < 8; nf++)
                mma_f16(acc_s[nf], qf[ks], &b[nf >> 1][(nf & 1) * 2]);
        }

        // online softmax (ex2); P in registers
        uint32_t ph[8][2];
        #pragma unroll
        for (int hh = 0; hh < 2; hh++) {
            float rmax = -1e30f;
            #pragma unroll
            for (int nf = 0; nf < 8; nf++)
                rmax = fmaxf(rmax, fmaxf(acc_s[nf][2*hh], acc_s[nf][2*hh+1]));
            rmax = fmaxf(rmax, __shfl_xor_sync(0xffffffffu, rmax, 1));
            rmax = fmaxf(rmax, __shfl_xor_sync(0xffffffffu, rmax, 2));
            float mn = fmaxf(mrow[hh], rmax);
            float scale = ex2(mrow[hh] - mn);
            #pragma unroll
            for (int nf = 0; nf < 8; nf++) {
                __half2 hp = __floats2half2_rn(ex2(acc_s[nf][2*hh]   - mn),
                                               ex2(acc_s[nf][2*hh+1] - mn));
                ph[nf][hh] = *(uint32_t*)&hp;
            }
            mrow[hh] = mn;
            #pragma unroll
            for (int nf = 0; nf < 8; nf++) {
                acc_o[nf][2*hh]   *= scale;
                acc_o[nf][2*hh+1] *= scale;
            }
            acc_l[2*hh]   *= scale;
            acc_l[2*hh+1] *= scale;
        }

        // O += P @ V ; l += P @ ones (9th n-fragment)
        const uint32_t v0_u = vs_u + (uint32_t)(s * 64 * ALD) * 2;
        #pragma unroll
        for (int ks = 0; ks < 4; ks++) {
            uint32_t a[4] = { ph[2*ks][0], ph[2*ks][1],
                              ph[2*ks+1][0], ph[2*ks+1][1] };
            const uint32_t rowaddr = v0_u +
                (uint32_t)((ks * 16 + (lane & 15)) * ALD) * 2;
            #pragma unroll
            for (int nf = 0; nf < 9; nf++) {
                uint32_t b0, b1;
                ldsm_x2_trans(b0, b1, rowaddr + (uint32_t)(nf * 8) * 2);
                uint32_t bfr[2] = { b0, b1 };
                mma_f16(nf < 8 ? acc_o[nf] : acc_l, a, bfr);
            }
        }
        __syncthreads();
    }

    // l lives in acc_l[0]/acc_l[2] of the lr==0 lane of each quad
    #pragma unroll
    for (int hh = 0; hh < 2; hh++) {
        float lsum = __shfl_sync(0xffffffffu, acc_l[2*hh], lane & 28);
        float inv = 1.f / lsum;
        int row = q0 + m0 + lq + 8 * hh;
        __half* orow = res + (size_t)(b * Tt + row) * EMBv + h * 64;
        #pragma unroll
        for (int nf = 0; nf < 8; nf++)
            *(__half2*)(orow + nf * 8 + 2 * lr) =
                __floats2half2_rn(acc_o[nf][2*hh] * inv, acc_o[nf][2*hh+1] * inv);
    }
}

// ---------------- fused residual add + LayerNorm (fp16 increment) ----------
__global__ __launch_bounds__(256)
void add_ln_kernel(const float* __restrict__ xa, const __half* __restrict__ xb,
                   const float* __restrict__ g, const float* __restrict__ bt,
                   float* __restrict__ out, __half* __restrict__ out_r)
{
    const int row = blockIdx.x;
    const int tid = threadIdx.x;
    const float* pa = xa + (size_t)row*EMBv;
    const __half* pb = xb + (size_t)row*EMBv;
    float v[4], s = 0.f, s2 = 0.f;
    #pragma unroll
    for (int i = 0; i < 4; i++) {
        int c = tid + i*256;
        v[i] = pa[c] + __half2float(pb[c]);
        s += v[i]; s2 += v[i]*v[i];
    }
    #pragma unroll
    for (int off = 16; off > 0; off >>= 1) {
        s  += __shfl_xor_sync(0xffffffffu, s,  off);
        s2 += __shfl_xor_sync(0xffffffffu, s2, off);
    }
    __shared__ float rs[8], rs2[8];
    int w = tid >> 5, lane = tid & 31;
    if (lane == 0) { rs[w] = s; rs2[w] = s2; }
    __syncthreads();
    if (w == 0) {
        float a  = (lane < 8) ? rs[lane]  : 0.f;
        float a2 = (lane < 8) ? rs2[lane] : 0.f;
        #pragma unroll
        for (int off = 4; off > 0; off >>= 1) {
            a  += __shfl_xor_sync(0xffffffffu, a,  off);
            a2 += __shfl_xor_sync(0xffffffffu, a2, off);
        }
        if (lane == 0) { rs[0] = a; rs2[0] = a2; }
    }
    __syncthreads();
    float mean = rs[0] * (1.f/EMBv);
    float var  = rs2[0] * (1.f/EMBv) - mean*mean;
    float inv  = rsqrtf(var + 1e-5f);
    #pragma unroll
    for (int i = 0; i < 4; i++) {
        int c = tid + i*256;
        float o = (v[i] - mean)*inv*g[c] + bt[c];
        out[(size_t)row*EMBv + c] = o;
        if (out_r) out_r[(size_t)row*EMBv + c] = __float2half_rn(o);
    }
}

// ---------------- launch ----------------------------------------------------
extern "C" void kernel_launch(void* const* d_in, const int* in_sizes, int n_in,
                              void* d_out, int out_size)
{
    const float* x     = (const float*)d_in[0];
    const float* Wkqv  = (const float*)d_in[1];
    const float* Wproj = (const float*)d_in[2];
    const float* g1    = (const float*)d_in[3];
    const float* b1    = (const float*)d_in[4];
    const float* W1    = (const float*)d_in[5];
    const float* bff1  = (const float*)d_in[6];
    const float* W2    = (const float*)d_in[7];
    const float* bff2  = (const float*)d_in[8];
    const float* g2    = (const float*)d_in[9];
    const float* b2    = (const float*)d_in[10];
    float* out = (float*)d_out;

    __half *xh, *kqv, *res, *mha, *x1r, *hbuf, *ff, *wqt, *wtp, *wt1, *wt2;
    float  *x1;
    cudaGetSymbolAddress((void**)&xh,   g_xh);
    cudaGetSymbolAddress((void**)&kqv,  g_kqv);
    cudaGetSymbolAddress((void**)&res,  g_res);
    cudaGetSymbolAddress((void**)&mha,  g_mha);
    cudaGetSymbolAddress((void**)&x1,   g_x1);
    cudaGetSymbolAddress((void**)&x1r,  g_x1r);
    cudaGetSymbolAddress((void**)&hbuf, g_h);
    cudaGetSymbolAddress((void**)&ff,   g_ff);
    cudaGetSymbolAddress((void**)&wqt,  g_wqt);
    cudaGetSymbolAddress((void**)&wtp,  g_wtp);
    cudaGetSymbolAddress((void**)&wt1,  g_wt1);
    cudaGetSymbolAddress((void**)&wt2,  g_wt2);

    cudaFuncSetAttribute((const void*)mma_gemm<0,__half>,
        cudaFuncAttributeMaxDynamicSharedMemorySize, MMA_SMEM);
    cudaFuncSetAttribute((const void*)mma_gemm<1,__half>,
        cudaFuncAttributeMaxDynamicSharedMemorySize, MMA_SMEM);
    cudaFuncSetAttribute((const void*)mma_gemm<2,__half>,
        cudaFuncAttributeMaxDynamicSharedMemorySize, MMA_SMEM);
    cudaFuncSetAttribute((const void*)attn_mma,
        cudaFuncAttributeMaxDynamicSharedMemorySize, ATTN_SMEM);
    cudaFuncSetAttribute((const void*)kqv_mma,
        cudaFuncAttributeMaxDynamicSharedMemorySize, KQV_SMEM);

    // one-time (uncaptured first call) stream/event creation for the
    // weight-preprocessing side branch of the graph
    static cudaStream_t s_side = nullptr;
    static cudaEvent_t  s_fork = nullptr, s_join = nullptr;
    if (!s_side) {
        cudaStreamCreateWithFlags(&s_side, cudaStreamNonBlocking);
        cudaEventCreateWithFlags(&s_fork, cudaEventDisableTiming);
        cudaEventCreateWithFlags(&s_join, cudaEventDisableTiming);
    }

    // fork: side stream branches from the start of the graph
    cudaEventRecord(s_fork, 0);
    cudaStreamWaitEvent(s_side, s_fork, 0);

    // ---- main chain (attn_mma stays the 4th submitted launch for ncu) ----
    cvt_half_kernel<<<(NTOK*EMBv/4 + 255)/256, 256>>>(
        (const float4*)x, (__half2*)xh, NTOK*EMBv/4);
    transpose_kernel<<<dim3(192/32, Ss/32), dim3(32,8)>>>(Wkqv, wqt, Ss, 192);
    kqv_mma<<<(NTOK*Hh)/128, 192, KQV_SMEM>>>(xh, wqt, kqv);
    attn_mma<<<dim3(Bb*Hh, Tt/128), 256, ATTN_SMEM>>>(kqv, res);

    // ---- side branch: big-weight transposes, overlapped with kqv+attention
    transpose_kernel<<<dim3(EMBv/32, EMBv/32), dim3(32,8), 0, s_side>>>(
        Wproj, wtp, EMBv, EMBv);
    transpose_kernel<<<dim3(FF/32, EMBv/32), dim3(32,8), 0, s_side>>>(
        W1, wt1, EMBv, FF);
    transpose_kernel<<<dim3(EMBv/32, FF/32), dim3(32,8), 0, s_side>>>(
        W2, wt2, FF, EMBv);
    cudaEventRecord(s_join, s_side);

    // join before the first consumer of transposed weights
    cudaStreamWaitEvent(0, s_join, 0);

    mma_gemm<0,__half><<<dim3(EMBv/128, NTOK/128), 256, MMA_SMEM>>>(
        res, wtp, nullptr, mha, NTOK, EMBv, EMBv);
    add_ln_kernel<<<NTOK, 256>>>(x, mha, g1, b1, x1, x1r);
    mma_gemm<2,__half><<<dim3(FF/128, NTOK/128), 256, MMA_SMEM>>>(
        x1r, wt1, bff1, hbuf, NTOK, FF, EMBv);
    mma_gemm<1,__half><<<dim3(EMBv/128, NTOK/128), 256, MMA_SMEM>>>(
        hbuf, wt2, bff2, ff, NTOK, EMBv, FF);
    add_ln_kernel<<<NTOK, 256>>>(x1, ff, g2, b2, out, nullptr);
}